// round 12
// baseline (speedup 1.0000x reference)
#include <cuda_runtime.h>
#include <cuda_bf16.h>
#include <cstdint>

// ---------------- Problem constants ----------------
#define BATCH   2048
#define NCOLS   32
#define CATD    2000
#define HID     128
#define VTOT    64000

// ---------------- Device scratch (no allocs allowed) ----------------
__device__ __align__(16) __nv_bfloat16 g_Wb[VTOT * HID];      // 16 MB  bf16 W_dec
__device__ __align__(16) float         g_c[VTOT];             // 256 KB c[v]
__device__ __align__(16) __nv_bfloat16 g_delta[BATCH * HID];  // 512 KB bf16 (y - ybar)
__device__ __align__(16) __nv_bfloat16 g_WTb[VTOT * HID];     // 16 MB  W_enc^T [v][h] bf16

__device__ __forceinline__ uint32_t smem_to_u32(const void* p) {
    uint32_t a;
    asm("{ .reg .u64 t; cvta.to.shared.u64 t, %1; cvt.u32.u64 %0, t; }" : "=r"(a) : "l"(p));
    return a;
}

#define CP_ASYNC_CG16(dst_smem, src_gmem) \
    asm volatile("cp.async.cg.shared.global [%0], [%1], 16;" \
        :: "r"(dst_smem), "l"(src_gmem) : "memory")
#define CP_ASYNC_COMMIT() asm volatile("cp.async.commit_group;" ::: "memory")
#define CP_ASYNC_WAIT(n)  asm volatile("cp.async.wait_group %0;" :: "n"(n) : "memory")

__device__ __forceinline__ void stg_cs_v4(float* p, float x, float y, float z, float w) {
    asm volatile("st.global.cs.v4.f32 [%0], {%1,%2,%3,%4};"
                 :: "l"(p), "f"(x), "f"(y), "f"(z), "f"(w) : "memory");
}

// ---------------- Kernel 0: fused pre — transpose (32-v slabs) + prep ----------------
#define TP_BLOCKS   (VTOT / 32)     // 2000
#define PREP_BLOCKS (VTOT / 8)      // 8000

__global__ void __launch_bounds__(256) pre_kernel(const float* __restrict__ Wenc,
                                                  const float* __restrict__ Wdec,
                                                  const float* __restrict__ benc,
                                                  const float* __restrict__ bdec) {
    __shared__ float st[32 * 129];
    if (blockIdx.x < TP_BLOCKS) {
        int v0 = blockIdx.x * 32;
        int t  = threadIdx.x;
        #pragma unroll
        for (int it = 0; it < 16; ++it) {
            int idx = it * 256 + t;
            int v = idx & 31;
            int h = idx >> 5;
            st[v * 129 + h] = Wenc[(size_t)h * VTOT + v0 + v];
        }
        __syncthreads();
        #pragma unroll
        for (int it = 0; it < 4; ++it) {
            int idx = it * 256 + t;
            int h4 = (idx & 31) * 4;
            int v  = idx >> 5;
            __nv_bfloat162 p0 = __floats2bfloat162_rn(st[v * 129 + h4 + 0], st[v * 129 + h4 + 1]);
            __nv_bfloat162 p1 = __floats2bfloat162_rn(st[v * 129 + h4 + 2], st[v * 129 + h4 + 3]);
            uint2 pk;
            pk.x = *reinterpret_cast<uint32_t*>(&p0);
            pk.y = *reinterpret_cast<uint32_t*>(&p1);
            *reinterpret_cast<uint2*>(g_WTb + (size_t)(v0 + v) * HID + h4) = pk;
        }
    } else {
        int gw   = ((blockIdx.x - TP_BLOCKS) * 256 + threadIdx.x) >> 5;
        int lane = threadIdx.x & 31;
        if (gw >= VTOT) return;

        float4 w = *reinterpret_cast<const float4*>(Wdec + (size_t)gw * HID + lane * 4);

        float b0 = benc[lane * 4 + 0], b1 = benc[lane * 4 + 1];
        float b2 = benc[lane * 4 + 2], b3 = benc[lane * 4 + 3];
        float dot = w.x / (1.0f + __expf(-b0)) + w.y / (1.0f + __expf(-b1))
                  + w.z / (1.0f + __expf(-b2)) + w.w / (1.0f + __expf(-b3));

        __nv_bfloat162 p0 = __floats2bfloat162_rn(w.x, w.y);
        __nv_bfloat162 p1 = __floats2bfloat162_rn(w.z, w.w);
        uint2 pk;
        pk.x = *reinterpret_cast<uint32_t*>(&p0);
        pk.y = *reinterpret_cast<uint32_t*>(&p1);
        *reinterpret_cast<uint2*>(g_Wb + (size_t)gw * HID + lane * 4) = pk;

        #pragma unroll
        for (int o = 16; o > 0; o >>= 1) dot += __shfl_xor_sync(0xffffffffu, dot, o);
        if (lane == 0) g_c[gw] = dot + bdec[gw];
    }
}

// ---------------- Kernel 2: encode (bf16 gather rows, fp32 accumulate) ----------------
__global__ void __launch_bounds__(256) encode_kernel(const int* __restrict__ xcat,
                                                     const float* __restrict__ benc,
                                                     float* __restrict__ yout) {
    int wid  = threadIdx.x >> 5;
    int lane = threadIdx.x & 31;
    int b    = blockIdx.x * 8 + wid;

    int gidx = xcat[b * NCOLS + lane] + lane * CATD;

    float a0 = 0.f, a1 = 0.f, a2 = 0.f, a3 = 0.f;
    #pragma unroll
    for (int i = 0; i < NCOLS; ++i) {
        int gi = __shfl_sync(0xffffffffu, gidx, i);
        uint2 pk = *reinterpret_cast<const uint2*>(g_WTb + (size_t)gi * HID + lane * 4);
        __nv_bfloat162 p0 = *reinterpret_cast<__nv_bfloat162*>(&pk.x);
        __nv_bfloat162 p1 = *reinterpret_cast<__nv_bfloat162*>(&pk.y);
        a0 += __bfloat162float(p0.x); a1 += __bfloat162float(p0.y);
        a2 += __bfloat162float(p1.x); a3 += __bfloat162float(p1.y);
    }

    float4 be = *reinterpret_cast<const float4*>(benc + lane * 4);
    float y0 = 1.0f / (1.0f + __expf(-(a0 + be.x)));
    float y1 = 1.0f / (1.0f + __expf(-(a1 + be.y)));
    float y2 = 1.0f / (1.0f + __expf(-(a2 + be.z)));
    float y3 = 1.0f / (1.0f + __expf(-(a3 + be.w)));
    if (yout) {
        float4 yv = {y0, y1, y2, y3};
        *reinterpret_cast<float4*>(yout + (size_t)b * HID + lane * 4) = yv;
    }
    float d0 = y0 - 1.0f / (1.0f + __expf(-be.x));
    float d1 = y1 - 1.0f / (1.0f + __expf(-be.y));
    float d2 = y2 - 1.0f / (1.0f + __expf(-be.z));
    float d3 = y3 - 1.0f / (1.0f + __expf(-be.w));
    __nv_bfloat162 p0 = __floats2bfloat162_rn(d0, d1);
    __nv_bfloat162 p1 = __floats2bfloat162_rn(d2, d3);
    uint2 pk;
    pk.x = *reinterpret_cast<uint32_t*>(&p0);
    pk.y = *reinterpret_cast<uint32_t*>(&p1);
    *reinterpret_cast<uint2*>(g_delta + (size_t)b * HID + lane * 4) = pk;
}

// ---------------- Kernel 3: decode GEMM — persistent CTAs, B-resident per nb-run ------------
// 304 persistent CTAs; units = (nb, mt) ordered nb-major (u = nb*16 + mt), static partition.
// B tile fragments hoisted to registers when nb changes (B smem then reusable);
// A tiles double-buffered via cp.async. mf-outer compute + STG.128 epilogue.

#define TILE_M 128
#define TILE_N 128
#define MTILES 16                        // BATCH / TILE_M
#define NBLKS  (VTOT / TILE_N)           // 500
#define NUNITS (NBLKS * MTILES)          // 8000
#define NCTA   304
#define SROWB  272
#define TILE_BYTES (128 * SROWB)         // 34816
#define SM_TOTAL (3 * TILE_BYTES)        // 104448 (B + 2x A)

__device__ __forceinline__ void ldmatrix_x4(uint32_t (&r)[4], uint32_t addr) {
    asm volatile("ldmatrix.sync.aligned.m8n8.x4.shared.b16 {%0,%1,%2,%3}, [%4];"
                 : "=r"(r[0]), "=r"(r[1]), "=r"(r[2]), "=r"(r[3]) : "r"(addr));
}
__device__ __forceinline__ void mma_bf16(float (&d)[4], const uint32_t (&a)[4], const uint32_t* b) {
    asm volatile(
        "mma.sync.aligned.m16n8k16.row.col.f32.bf16.bf16.f32 "
        "{%0,%1,%2,%3}, {%4,%5,%6,%7}, {%8,%9}, {%0,%1,%2,%3};"
        : "+f"(d[0]), "+f"(d[1]), "+f"(d[2]), "+f"(d[3])
        : "r"(a[0]), "r"(a[1]), "r"(a[2]), "r"(a[3]), "r"(b[0]), "r"(b[1]));
}

__device__ __forceinline__ void load_B_tile(uint32_t sdst, const char* src, int tid) {
    #pragma unroll
    for (int it = 0; it < 8; ++it) {
        int idx = it * 256 + tid;
        int row = idx >> 4;
        int ch  = (idx & 15) * 16;
        int gg  = row & 15;
        int q   = gg >> 2, r = gg & 3;
        int slot = (r < 2) ? (q * 2 + r) : (8 + q * 2 + (r & 1));
        int prow = (row & ~15) | slot;
        CP_ASYNC_CG16(sdst + prow * SROWB + ch, src + row * 256 + ch);
    }
}
__device__ __forceinline__ void load_A_tile(uint32_t sdst, const char* src, int tid) {
    #pragma unroll
    for (int it = 0; it < 8; ++it) {
        int idx = it * 256 + tid;
        int row = idx >> 4;
        int ch  = (idx & 15) * 16;
        CP_ASYNC_CG16(sdst + row * SROWB + ch, src + row * 256 + ch);
    }
}

__global__ void __launch_bounds__(256, 2) decode_gemm(float* __restrict__ zout) {
    extern __shared__ char smem[];
    uint32_t sbase = smem_to_u32(smem);
    int tid  = threadIdx.x;
    int wid  = tid >> 5;
    int lane = tid & 31;
    int k    = blockIdx.x;

    int u0 = (int)(((long long)k * NUNITS) / NCTA);
    int u1 = (int)(((long long)(k + 1) * NUNITS) / NCTA);
    if (u0 >= u1) return;

    int nb0 = u0 / MTILES;
    int mt0 = u0 % MTILES;

    // ---- preload first B tile + first A tile ----
    load_B_tile(sbase, reinterpret_cast<const char*>(g_Wb + (size_t)nb0 * TILE_N * HID), tid);
    load_A_tile(sbase + TILE_BYTES,
                reinterpret_cast<const char*>(g_delta + (size_t)mt0 * TILE_M * HID), tid);
    CP_ASYNC_COMMIT();

    int wm = wid & 1;
    int wn = wid >> 1;
    int j  = lane & 3;
    int colLoc = wn * 32 + j * 4;

    uint32_t aOff = (uint32_t)(wm * 64 + (lane & 15)) * SROWB + ((lane >> 4) << 4);
    uint32_t bOff = (uint32_t)(wn * 32 + ((lane >> 4) << 3) + (lane & 7)) * SROWB
                  + (((lane >> 3) & 1) << 4);

    CP_ASYNC_WAIT(0);
    __syncthreads();

    uint32_t ball[8][2][4];
    float4 cv[2];
    size_t colG = 0;

    int curnb = -1;
    int buf = 0;
    #pragma unroll 1
    for (int u = u0; u < u1; ++u) {
        int nb = u / MTILES;
        int mt = u % MTILES;

        if (nb != curnb) {
            // hoist B fragments (B smem -> regs); smem B region becomes reusable after sync
            #pragma unroll
            for (int ks = 0; ks < 8; ++ks)
                #pragma unroll
                for (int p = 0; p < 2; ++p)
                    ldmatrix_x4(ball[ks][p],
                                sbase + bOff + (uint32_t)p * 16u * SROWB + (uint32_t)ks * 32u);
            const float* ctab = g_c + (size_t)nb * TILE_N;
            cv[0] = *reinterpret_cast<const float4*>(ctab + colLoc);
            cv[1] = *reinterpret_cast<const float4*>(ctab + colLoc + 16);
            colG = (size_t)nb * TILE_N + colLoc;
            curnb = nb;
        }

        // ---- prefetch next unit ----
        bool more = (u + 1 < u1);
        if (more) {
            int nnb = (u + 1) / MTILES;
            int nmt = (u + 1) % MTILES;
            if (nnb != nb) {
                __syncthreads();   // all warps must have hoisted ball before B smem overwrite
                load_B_tile(sbase, reinterpret_cast<const char*>(g_Wb + (size_t)nnb * TILE_N * HID), tid);
            }
            load_A_tile(sbase + TILE_BYTES * (1 + (buf ^ 1)),
                        reinterpret_cast<const char*>(g_delta + (size_t)nmt * TILE_M * HID), tid);
            CP_ASYNC_COMMIT();
        }

        // ---- compute + store this tile ----
        uint32_t aBase = sbase + TILE_BYTES * (1 + buf) + aOff;
        int rowBase = mt * TILE_M + wm * 64 + (lane >> 2);

        #pragma unroll
        for (int mf = 0; mf < 4; ++mf) {
            float acc[4][4];
            #pragma unroll
            for (int jj = 0; jj < 4; ++jj)
                #pragma unroll
                for (int kk = 0; kk < 4; ++kk) acc[jj][kk] = 0.0f;

            #pragma unroll
            for (int ks = 0; ks < 8; ++ks) {
                uint32_t a[4];
                ldmatrix_x4(a, aBase + (uint32_t)mf * 16u * SROWB + (uint32_t)ks * 32u);
                #pragma unroll
                for (int nf = 0; nf < 4; ++nf)
                    mma_bf16(acc[nf], a, &ball[ks][nf >> 1][(nf & 1) * 2]);
            }

            float* z0 = zout + (size_t)(rowBase + mf * 16) * VTOT + colG;
            float* z1 = z0 + 8 * VTOT;
            stg_cs_v4(z0,      acc[0][0] + cv[0].x, acc[0][1] + cv[0].y,
                               acc[1][0] + cv[0].z, acc[1][1] + cv[0].w);
            stg_cs_v4(z1,      acc[0][2] + cv[0].x, acc[0][3] + cv[0].y,
                               acc[1][2] + cv[0].z, acc[1][3] + cv[0].w);
            stg_cs_v4(z0 + 16, acc[2][0] + cv[1].x, acc[2][1] + cv[1].y,
                               acc[3][0] + cv[1].z, acc[3][1] + cv[1].w);
            stg_cs_v4(z1 + 16, acc[2][2] + cv[1].x, acc[2][3] + cv[1].y,
                               acc[3][2] + cv[1].z, acc[3][3] + cv[1].w);
        }

        if (more) {
            CP_ASYNC_WAIT(0);
            __syncthreads();
            buf ^= 1;
        }
    }
}

// ---------------- Launch ----------------
extern "C" void kernel_launch(void* const* d_in, const int* in_sizes, int n_in,
                              void* d_out, int out_size) {
    const int*   xcat = (const int*)d_in[0];
    const float* Wenc = (const float*)d_in[1];
    const float* benc = (const float*)d_in[2];
    const float* Wdec = (const float*)d_in[3];
    const float* bdec = (const float*)d_in[4];

    float* out = (float*)d_out;
    long long ztotal = (long long)BATCH * VTOT;
    long long zoff   = (long long)out_size - ztotal;
    if (zoff < 0) zoff = 0;
    float* zout = out + zoff;
    float* yout = (zoff >= (long long)BATCH * HID) ? out : nullptr;

    cudaFuncSetAttribute(decode_gemm, cudaFuncAttributeMaxDynamicSharedMemorySize, SM_TOTAL);

    pre_kernel<<<TP_BLOCKS + PREP_BLOCKS, 256>>>(Wenc, Wdec, benc, bdec);
    encode_kernel<<<BATCH / 8, 256>>>(xcat, benc, yout);
    decode_gemm<<<NCTA, 256, SM_TOTAL>>>(zout);
}